// round 16
// baseline (speedup 1.0000x reference)
#include <cuda_runtime.h>
#include <cuda_fp16.h>
#include <cstdint>

#define NN 100000
#define NE 6400000
#define F_IN 128
#define HID 16

// ---------------- static device scratch ----------------
__device__ unsigned long long g_pack[NN];  // (count<<48) | fixed-point weight sum
__device__ float g_deg[NN];          // dis = rsqrt(deg) after k_disbase
__device__ int   g_cnt[NN];
__device__ int   g_base[NN];
__device__ int   g_cur[NN];
__device__ int   g_total;
__device__ int   g_is64;
struct __align__(8) ES { int s; float nr; };   // {src, w}
__device__ ES    g_pw[NE];           // edge-order packed {src, w} (coalesced)
__device__ int   g_dstA[NE];         // edge-order dst
__device__ ES    g_es[NE];           // dst-grouped records {src, w}
__device__ __align__(128) __half g_yh[NN * HID];   // y' = dis*y, fp16 (32B/row)
__device__ __align__(128) float  g_acc[NN * HID];
__device__ float g_y1[NN];           // y1' = dis*y1
__device__ float g_acc1[NN];

#define FIXS 268435456.0f          // 2^28
#define FIXI (1.0f / 268435456.0f)

// ---------------- kernels ----------------

__global__ void k_init(const void* edges, float* out) {
    int i = blockIdx.x * blockDim.x + threadIdx.x;
    if (i < NN) g_pack[i] = 0ull;
    if (i == 0) {
        g_total = 0; out[0] = 0.0f;
        const unsigned long long* e64 = (const unsigned long long*)edges;
        int all0 = 1;
        for (int k = 0; k < 64; k++)
            if ((e64[k] >> 32) != 0ull) { all0 = 0; break; }
        g_is64 = all0;
    }
}

// degree RED + write packed {s,w} and dst arrays (coalesced)
__global__ void k_deg(const void* __restrict__ edges, const float* __restrict__ w) {
    int e = blockIdx.x * blockDim.x + threadIdx.x;
    if (e >= NE) return;
    int s, d;
    if (g_is64) {
        const long long* e64 = (const long long*)edges;
        s = (int)e64[e];
        d = (int)e64[NE + e];
    } else {
        const int* e32 = (const int*)edges;
        s = e32[e];
        d = e32[NE + e];
    }
    ES r;
    if ((unsigned)s >= NN || (unsigned)d >= NN) {
        r.s = -1; r.nr = 0.f; g_pw[e] = r; g_dstA[e] = 0; return;
    }
    r.s = s; r.nr = w[e];
    g_pw[e]   = r;
    g_dstA[e] = d;
    unsigned long long p = (1ull << 48) | (unsigned long long)(w[e] * FIXS + 0.5f);
    atomicAdd(&g_pack[d], p);
}

// unpack -> dis = rsqrt(1 + degsum); cnt; segment bases via warp-aggregated alloc
__global__ void k_disbase() {
    int i = blockIdx.x * blockDim.x + threadIdx.x;
    int lane = threadIdx.x & 31;
    int c = 0;
    if (i < NN) {
        unsigned long long v = g_pack[i];
        c = (int)(v >> 48);
        float deg = 1.0f + (float)(v & 0xFFFFFFFFFFFFull) * FIXI;
        g_deg[i] = rsqrtf(deg);
        g_cnt[i] = c;
    }
    int sc = c;
#pragma unroll
    for (int o = 1; o < 32; o <<= 1) {
        int v = __shfl_up_sync(0xffffffffu, sc, o);
        if (lane >= o) sc += v;
    }
    int wtot = __shfl_sync(0xffffffffu, sc, 31);
    int wbase = 0;
    if (lane == 31) wbase = atomicAdd(&g_total, wtot);
    wbase = __shfl_sync(0xffffffffu, wbase, 31);
    if (i < NN) {
        int b = wbase + sc - c;
        g_base[i] = b;
        g_cur[i]  = b;
    }
}

// scatter: NO gathers -- stream {s,w}, cursor atomic, 8B store
__global__ void k_scatter() {
    int e = blockIdx.x * blockDim.x + threadIdx.x;
    if (e >= NE) return;
    ES r = g_pw[e];
    if (r.s < 0) return;
    int d = g_dstA[e];
    int pos = atomicAdd(&g_cur[d], 1);
    if (pos < NE) g_es[pos] = r;
}

// layer 1 transform: y' = dis * (x @ W1), stored fp16
__global__ void k_xform1(const float* __restrict__ x, const float* __restrict__ W) {
    __shared__ float Ws[F_IN * HID];
    __shared__ float xs[16][F_IN + 4];
    int t = threadIdx.x;
    int node0 = blockIdx.x * 16;

    for (int i = t; i < F_IN * HID; i += 256) Ws[i] = W[i];
    const float* xb = x + (size_t)node0 * F_IN;
#pragma unroll
    for (int j = 0; j < 8; j++) {
        int f = t + 256 * j;
        xs[f >> 7][f & 127] = xb[f];
    }
    __syncthreads();

    int ln = t >> 4;
    int h  = t & 15;
    float acc = 0.f;
#pragma unroll
    for (int k = 0; k < F_IN; k++)
        acc = fmaf(xs[ln][k], Ws[k * HID + h], acc);
    int node = node0 + ln;
    g_yh[node * HID + h] = __float2half_rn(g_deg[node] * acc);
}

// mid transform: r = relu(acc + b_prev); y' = dis * (r @ W), stored fp16
__global__ void k_xform_mid(const float* __restrict__ W, const float* __restrict__ b) {
    __shared__ float Ws[HID * HID];
    __shared__ float bs[HID];
    int t = threadIdx.x;
    if (t < HID * HID) Ws[t] = W[t];
    if (t < HID)       bs[t] = b[t];
    __syncthreads();
    int i = blockIdx.x * blockDim.x + t;
    if (i >= NN) return;

    const float4* av = (const float4*)(g_acc + (size_t)i * HID);
    float r[HID];
#pragma unroll
    for (int q = 0; q < 4; q++) {
        float4 a = av[q];
        r[q*4+0] = fmaxf(a.x + bs[q*4+0], 0.f);
        r[q*4+1] = fmaxf(a.y + bs[q*4+1], 0.f);
        r[q*4+2] = fmaxf(a.z + bs[q*4+2], 0.f);
        r[q*4+3] = fmaxf(a.w + bs[q*4+3], 0.f);
    }
    float dis = g_deg[i];
    float o[HID];
#pragma unroll
    for (int h = 0; h < HID; h++) {
        float s = 0.f;
#pragma unroll
        for (int k = 0; k < HID; k++) s = fmaf(r[k], Ws[k * HID + h], s);
        o[h] = dis * s;
    }
    __half2 hbuf[8];
#pragma unroll
    for (int k = 0; k < 8; k++) hbuf[k] = __floats2half2_rn(o[2*k], o[2*k+1]);
    uint4* yv = (uint4*)(g_yh + (size_t)i * HID);
    yv[0] = *(uint4*)&hbuf[0];
    yv[1] = *(uint4*)&hbuf[4];
}

// layer 4 transform: width 16 -> 1; y1' = dis * out
__global__ void k_xform4(const float* __restrict__ W, const float* __restrict__ b) {
    __shared__ float Ws[HID];
    __shared__ float bs[HID];
    int t = threadIdx.x;
    if (t < HID) { Ws[t] = W[t]; bs[t] = b[t]; }
    __syncthreads();
    int i = blockIdx.x * blockDim.x + t;
    if (i >= NN) return;

    const float4* av = (const float4*)(g_acc + (size_t)i * HID);
    float s = 0.f;
#pragma unroll
    for (int q = 0; q < 4; q++) {
        float4 a = av[q];
        s = fmaf(fmaxf(a.x + bs[q*4+0], 0.f), Ws[q*4+0], s);
        s = fmaf(fmaxf(a.y + bs[q*4+1], 0.f), Ws[q*4+1], s);
        s = fmaf(fmaxf(a.z + bs[q*4+2], 0.f), Ws[q*4+2], s);
        s = fmaf(fmaxf(a.w + bs[q*4+3], 0.f), Ws[q*4+3], s);
    }
    g_y1[i] = g_deg[i] * s;
}

// hot kernel: warp-per-node aggregation; out = dis*(acc + y'_self)
__global__ void __launch_bounds__(256) k_agg16() {
    __shared__ ES stage[8][32];
    int wid  = threadIdx.x >> 5;
    int lane = threadIdx.x & 31;
    int node = blockIdx.x * 8 + wid;
    if (node >= NN) return;
    int beg = g_base[node];
    int cnt = g_cnt[node];
    int h = lane & 15;
    int half = lane >> 4;

    float acc = 0.f;
    int nfull = cnt & ~31;
    for (int c0 = 0; c0 < nfull; c0 += 32) {
        stage[wid][lane] = g_es[beg + c0 + lane];
        __syncwarp();
#pragma unroll
        for (int j = 0; j < 32; j += 2) {
            ES e = stage[wid][j + half];
            acc = fmaf(e.nr, __half2float(g_yh[e.s * HID + h]), acc);
        }
        __syncwarp();
    }
    int rem = cnt - nfull;
    if (rem) {
        if (lane < rem) stage[wid][lane] = g_es[beg + nfull + lane];
        __syncwarp();
        for (int j = 0; j < rem; j += 2) {
            int idx = j + half;
            if (idx < rem) {
                ES e = stage[wid][idx];
                acc = fmaf(e.nr, __half2float(g_yh[e.s * HID + h]), acc);
            }
        }
        __syncwarp();
    }
    acc += __shfl_down_sync(0xffffffffu, acc, 16);
    if (lane < 16) {
        float dis = g_deg[node];
        float selfp = __half2float(g_yh[node * HID + h]);
        g_acc[node * HID + h] = dis * (acc + selfp);
    }
}

// width-1 aggregation: out = dis*(acc + y1'_self)
__global__ void __launch_bounds__(256) k_agg1() {
    int wid  = threadIdx.x >> 5;
    int lane = threadIdx.x & 31;
    int node = blockIdx.x * 8 + wid;
    if (node >= NN) return;
    int beg = g_base[node];
    int cnt = g_cnt[node];

    float acc = 0.f;
    for (int c0 = lane; c0 < cnt; c0 += 32) {
        ES e = g_es[beg + c0];
        acc = fmaf(e.nr, g_y1[e.s], acc);
    }
#pragma unroll
    for (int o = 16; o; o >>= 1) acc += __shfl_down_sync(0xffffffffu, acc, o);
    if (lane == 0) {
        float dis = g_deg[node];
        g_acc1[node] = dis * (acc + g_y1[node]);
    }
}

// final: mean over nodes of relu(acc1 + b4)
__global__ void k_mean(const float* __restrict__ b4, float* out) {
    int i = blockIdx.x * blockDim.x + threadIdx.x;
    float v = 0.f;
    if (i < NN) v = fmaxf(g_acc1[i] + b4[0], 0.f) * (1.0f / (float)NN);
#pragma unroll
    for (int o = 16; o; o >>= 1) v += __shfl_down_sync(0xffffffffu, v, o);
    __shared__ float ws[8];
    if ((threadIdx.x & 31) == 0) ws[threadIdx.x >> 5] = v;
    __syncthreads();
    if (threadIdx.x < 8) {
        float s = ws[threadIdx.x];
#pragma unroll
        for (int o = 4; o; o >>= 1) s += __shfl_down_sync(0xffu, s, o);
        if (threadIdx.x == 0) atomicAdd(out, s);
    }
}

// ---------------- launch ----------------
extern "C" void kernel_launch(void* const* d_in, const int* in_sizes, int n_in,
                              void* d_out, int out_size) {
    const float* x     = (const float*)d_in[0];
    const void*  edges = d_in[1];
    const float* w     = (const float*)d_in[2];
    const float* W1 = (const float*)d_in[3];
    const float* b1 = (const float*)d_in[4];
    const float* W2 = (const float*)d_in[5];
    const float* b2 = (const float*)d_in[6];
    const float* W3 = (const float*)d_in[7];
    const float* b3 = (const float*)d_in[8];
    const float* W4 = (const float*)d_in[9];
    const float* b4 = (const float*)d_in[10];
    float* out = (float*)d_out;

    const int TB = 256;
    const int GN = (NN + TB - 1) / TB;       // 391
    const int GE = (NE + TB - 1) / TB;       // 25000
    const int GS = NN / 16;                  // 6250
    const int GW = (NN + 7) / 8;             // 12500

    k_init<<<GN, TB>>>(edges, out);          // 0
    k_deg<<<GE, TB>>>(edges, w);             // 1
    k_disbase<<<GN, TB>>>();                 // 2
    k_scatter<<<GE, TB>>>();                 // 3

    k_xform1<<<GS, TB>>>(x, W1);             // 4
    k_agg16<<<GW, TB>>>();                   // 5
    k_xform_mid<<<GN, TB>>>(W2, b1);         // 6
    k_agg16<<<GW, TB>>>();                   // 7
    k_xform_mid<<<GN, TB>>>(W3, b2);         // 8
    k_agg16<<<GW, TB>>>();                   // 9
    k_xform4<<<GN, TB>>>(W4, b3);            // 10
    k_agg1<<<GW, TB>>>();                    // 11
    k_mean<<<GN, TB>>>(b4, out);             // 12
}